// round 2
// baseline (speedup 1.0000x reference)
#include <cuda_runtime.h>
#include <stdint.h>

// Problem constants (fixed by the dataset)
#define BB   256          // batch (images / segments)
#define DD   512          // embedding dim
#define HWQ  256          // H*W spatial positions
#define D4   (DD/4)       // float4 columns per row = 128

// Scratch (no device allocation allowed)
__device__ float     g_zimg[BB * DD];
__device__ float     g_zsnd[BB * DD];
__device__ long long g_off[BB + 1];

// ---------------------------------------------------------------------------
// Kernel 1: inclusive scan of snd_splits -> segment offsets.
// Dtype-robust: try int32 first (always an in-bounds read); if the total
// doesn't equal T, the buffer must really be int64 -> rescan as int64.
// One block of BB threads, Hillis–Steele in shared memory.
// ---------------------------------------------------------------------------
__global__ void scan_splits_kernel(const int* __restrict__ p32, long long T) {
    __shared__ long long s[BB];
    int t = threadIdx.x;

    // pass 1: int32 interpretation
    s[t] = (long long)p32[t];
    __syncthreads();
#pragma unroll
    for (int off = 1; off < BB; off <<= 1) {
        long long v = (t >= off) ? s[t - off] : 0LL;
        __syncthreads();
        s[t] += v;
        __syncthreads();
    }
    long long tot = s[BB - 1];   // uniform across block (post-sync)

    if (tot != T) {
        // pass 2: int64 interpretation (buffer is 2 KiB in this case)
        const long long* p64 = (const long long*)p32;
        __syncthreads();
        s[t] = p64[t];
        __syncthreads();
#pragma unroll
        for (int off = 1; off < BB; off <<= 1) {
            long long v = (t >= off) ? s[t - off] : 0LL;
            __syncthreads();
            s[t] += v;
            __syncthreads();
        }
    }

    g_off[t + 1] = s[t];
    if (t == 0) g_off[0] = 0LL;
}

// ---------------------------------------------------------------------------
// Kernel 2: spatial mean pool. One warp per (b,d) pair; each lane loads
// 2 float4 (64 float4 = 256 floats per pair), warp-shuffle reduce.
// ---------------------------------------------------------------------------
__global__ void img_reduce_kernel(const float* __restrict__ Zimg) {
    int gwarp = (blockIdx.x * blockDim.x + threadIdx.x) >> 5;
    int lane  = threadIdx.x & 31;
    if (gwarp >= BB * DD) return;
    const float4* p = reinterpret_cast<const float4*>(Zimg + (size_t)gwarp * HWQ);
    float4 a = p[lane];
    float4 b = p[lane + 32];
    float s = (a.x + a.y) + (a.z + a.w) + (b.x + b.y) + (b.z + b.w);
#pragma unroll
    for (int o = 16; o > 0; o >>= 1)
        s += __shfl_down_sync(0xffffffffu, s, o);
    if (lane == 0)
        g_zimg[gwarp] = s * (1.0f / (float)HWQ);
}

// ---------------------------------------------------------------------------
// Kernel 3: ragged segment mean over Z_snd rows.
// One block per segment b. 512 threads = 4 row-slices x 128 float4 columns.
// Each thread accumulates its row-slice for one float4 column; combine in smem.
// ---------------------------------------------------------------------------
__global__ void snd_reduce_kernel(const float* __restrict__ Zsnd) {
    __shared__ float4 part[4][D4];
    int b     = blockIdx.x;
    int col   = threadIdx.x & (D4 - 1);   // 0..127
    int slice = threadIdx.x >> 7;         // 0..3

    long long start = g_off[b];
    long long end   = g_off[b + 1];
    long long len   = end - start;

    // row range for this slice
    long long r0 = start + (len * slice)       / 4;
    long long r1 = start + (len * (slice + 1)) / 4;

    const float4* p = reinterpret_cast<const float4*>(Zsnd);
    float4 acc = make_float4(0.f, 0.f, 0.f, 0.f);
    for (long long r = r0; r < r1; ++r) {
        float4 v = p[r * D4 + col];
        acc.x += v.x; acc.y += v.y; acc.z += v.z; acc.w += v.w;
    }
    part[slice][col] = acc;
    __syncthreads();

    if (slice == 0) {
        float4 a0 = part[0][col], a1 = part[1][col],
               a2 = part[2][col], a3 = part[3][col];
        float inv = (len > 0) ? (1.0f / (float)len) : 0.0f;
        float4 o;
        o.x = (a0.x + a1.x + a2.x + a3.x) * inv;
        o.y = (a0.y + a1.y + a2.y + a3.y) * inv;
        o.z = (a0.z + a1.z + a2.z + a3.z) * inv;
        o.w = (a0.w + a1.w + a2.w + a3.w) * inv;
        reinterpret_cast<float4*>(g_zsnd)[b * D4 + col] = o;
    }
}

// ---------------------------------------------------------------------------
// Kernel 4: broadcast writer.
// Output = [ M_img (B,B,D) | M_snd (B,B,D) ] as float4 stores.
//   M_img[i][j][:] = z_img[j][:]  -> index mod (B*D4) gives j*D4+c
//   M_snd[i][j][:] = z_snd[i][:]
// Sources are 512 KiB each -> L2-resident; this kernel is write-bound.
// ---------------------------------------------------------------------------
__global__ void broadcast_kernel(float4* __restrict__ out) {
    const size_t NIMG = (size_t)BB * BB * D4;  // float4 count of M_img
    size_t idx = (size_t)blockIdx.x * blockDim.x + threadIdx.x;
    const float4* zi = reinterpret_cast<const float4*>(g_zimg);
    const float4* zs = reinterpret_cast<const float4*>(g_zsnd);
    if (idx < NIMG) {
        size_t jc = idx & ((size_t)BB * D4 - 1);   // B*D4 = 32768, pow2
        out[idx] = zi[jc];
    } else {
        size_t rel = idx - NIMG;
        size_t i = rel >> 15;          // / (B*D4) = 32768
        size_t c = rel & (D4 - 1);     // % 128
        out[idx] = zs[i * D4 + c];
    }
}

// ---------------------------------------------------------------------------
extern "C" void kernel_launch(void* const* d_in, const int* in_sizes, int n_in,
                              void* d_out, int out_size) {
    // Identify inputs by element count (defensive against ordering):
    //   Z_img: B*D*H*W = 33,554,432   Z_snd: T*D = 16,777,216   splits: B = 256
    const float* Zimg   = nullptr;
    const float* Zsnd   = nullptr;
    const int*   splits = nullptr;
    long long    Tsnd   = 0;

    for (int i = 0; i < n_in; ++i) {
        if (in_sizes[i] == BB) {
            splits = (const int*)d_in[i];
        } else if (in_sizes[i] == BB * DD * HWQ) {
            Zimg = (const float*)d_in[i];
        } else {
            Zsnd = (const float*)d_in[i];
            Tsnd = (long long)(in_sizes[i] / DD);
        }
    }
    (void)out_size;

    // 1. segment offsets (dtype-robust scan)
    scan_splits_kernel<<<1, BB>>>(splits, Tsnd);

    // 2. image spatial mean: one warp per (b,d); 8 warps / 256-thread block
    {
        int pairs  = BB * DD;               // 131072 warps
        int blocks = pairs / 8;             // 16384 blocks of 256 threads
        img_reduce_kernel<<<blocks, 256>>>(Zimg);
    }

    // 3. segment mean
    snd_reduce_kernel<<<BB, 512>>>(Zsnd);

    // 4. broadcast write of both outputs
    {
        size_t total4 = (size_t)2 * BB * BB * D4;    // 33,554,432 float4
        int threads = 256;
        int blocks  = (int)(total4 / threads);       // 131072
        broadcast_kernel<<<blocks, threads>>>((float4*)d_out);
    }
}

// round 3
// speedup vs baseline: 1.1716x; 1.1716x over previous
#include <cuda_runtime.h>
#include <stdint.h>

#define BB   256          // batch (images / segments)
#define DD   512          // embedding dim
#define HWQ  256          // H*W spatial positions
#define D4   (DD/4)       // float4 columns per row = 128
#define NT   512          // threads per block

// ---------------------------------------------------------------------------
// One fused kernel, 2*BB blocks, no inter-block dependencies.
//   blocks [0, BB)      : snd path. Block b scans splits in-smem, reduces
//                         segment b of Z_snd to z_snd[b] (512 floats), then
//                         writes M_snd[b,:,:] = z_snd[b] x 256 (contiguous 512KiB).
//   blocks [BB, 2*BB)   : img path. Block j reduces Z_img[j] spatially to
//                         z_img[j], then writes M_img[i,j,:] for all i
//                         (256 x 2KiB coalesced rows at 512KiB stride).
// Output layout: [ M_img (B,B,D) | M_snd (B,B,D) ].
// ---------------------------------------------------------------------------
__global__ __launch_bounds__(NT)
void fused_meanpool_bcast(const float* __restrict__ Zimg,
                          const float* __restrict__ Zsnd,
                          const int*   __restrict__ splits,
                          float4*      __restrict__ out,
                          long long T) {
    __shared__ long long s_scan[BB];     // 2 KiB  (snd only)
    __shared__ float4    s_part[4][D4];  // 8 KiB  (snd only)
    __shared__ float     s_z[DD];        // 2 KiB  (both paths)

    const int t = threadIdx.x;

    if (blockIdx.x < BB) {
        // =================== SND PATH ===================
        const int b = blockIdx.x;

        // --- in-block inclusive scan of splits (dtype-robust) ---
        if (t < BB) s_scan[t] = (long long)splits[t];
        __syncthreads();
#pragma unroll
        for (int off = 1; off < BB; off <<= 1) {
            long long v = (t >= off && t < BB) ? s_scan[t - off] : 0LL;
            __syncthreads();
            if (t < BB) s_scan[t] += v;
            __syncthreads();
        }
        if (s_scan[BB - 1] != T) {
            // splits buffer is really int64
            const long long* p64 = (const long long*)splits;
            __syncthreads();
            if (t < BB) s_scan[t] = p64[t];
            __syncthreads();
#pragma unroll
            for (int off = 1; off < BB; off <<= 1) {
                long long v = (t >= off && t < BB) ? s_scan[t - off] : 0LL;
                __syncthreads();
                if (t < BB) s_scan[t] += v;
                __syncthreads();
            }
        }
        __syncthreads();
        const long long start = (b == 0) ? 0LL : s_scan[b - 1];
        const long long len   = s_scan[b] - start;

        // --- segment reduce: 4 row-slices x 128 float4 columns ---
        const int col   = t & (D4 - 1);
        const int slice = t >> 7;
        long long r0 = start + (len * slice)       / 4;
        long long r1 = start + (len * (slice + 1)) / 4;

        const float4* p = reinterpret_cast<const float4*>(Zsnd);
        float4 acc = make_float4(0.f, 0.f, 0.f, 0.f);
        for (long long r = r0; r < r1; ++r) {
            float4 v = __ldcs(&p[r * D4 + col]);
            acc.x += v.x; acc.y += v.y; acc.z += v.z; acc.w += v.w;
        }
        s_part[slice][col] = acc;
        __syncthreads();

        if (slice == 0) {
            float4 a0 = s_part[0][col], a1 = s_part[1][col],
                   a2 = s_part[2][col], a3 = s_part[3][col];
            float inv = (len > 0) ? (1.0f / (float)len) : 0.0f;
            float4 o;
            o.x = (a0.x + a1.x + a2.x + a3.x) * inv;
            o.y = (a0.y + a1.y + a2.y + a3.y) * inv;
            o.z = (a0.z + a1.z + a2.z + a3.z) * inv;
            o.w = (a0.w + a1.w + a2.w + a3.w) * inv;
            reinterpret_cast<float4*>(s_z)[col] = o;
        }
        __syncthreads();

        // --- write M_snd[b,:,:]: contiguous 512 KiB, value repeats per col ---
        float4 v = reinterpret_cast<const float4*>(s_z)[col];
        float4* dst = out + (size_t)(BB + b) * (BB * D4);   // NIMG4 + b*B*D4
        for (int k = t; k < BB * D4; k += NT)
            __stcs(&dst[k], v);

    } else {
        // =================== IMG PATH ===================
        const int j    = blockIdx.x - BB;
        const int wid  = t >> 5;
        const int lane = t & 31;

        // --- spatial reduce: 16 warps, each handles 32 d-rows of 64 float4 ---
        const float4* p = reinterpret_cast<const float4*>(
            Zimg + (size_t)j * DD * HWQ);
        for (int r = wid; r < DD; r += 16) {
            float4 a = __ldcs(&p[r * 64 + lane]);
            float4 b = __ldcs(&p[r * 64 + 32 + lane]);
            float s = (a.x + a.y) + (a.z + a.w) + (b.x + b.y) + (b.z + b.w);
#pragma unroll
            for (int o = 16; o > 0; o >>= 1)
                s += __shfl_down_sync(0xffffffffu, s, o);
            if (lane == 0)
                s_z[r] = s * (1.0f / (float)HWQ);
        }
        __syncthreads();

        // --- write M_img[i,j,:] for all i: 4 rows in flight x 128 cols ---
        const int col   = t & (D4 - 1);
        const int slice = t >> 7;
        float4 v = reinterpret_cast<const float4*>(s_z)[col];
        float4* base = out + (size_t)j * D4 + col;
        for (int i = slice; i < BB; i += 4)
            __stcs(base + (size_t)i * (BB * D4), v);
    }
}

// ---------------------------------------------------------------------------
extern "C" void kernel_launch(void* const* d_in, const int* in_sizes, int n_in,
                              void* d_out, int out_size) {
    // Identify inputs by element count:
    //   Z_img: 33,554,432   Z_snd: 16,777,216   splits: 256
    const float* Zimg   = nullptr;
    const float* Zsnd   = nullptr;
    const int*   splits = nullptr;
    long long    Tsnd   = 0;

    for (int i = 0; i < n_in; ++i) {
        if (in_sizes[i] == BB) {
            splits = (const int*)d_in[i];
        } else if (in_sizes[i] == BB * DD * HWQ) {
            Zimg = (const float*)d_in[i];
        } else {
            Zsnd = (const float*)d_in[i];
            Tsnd = (long long)(in_sizes[i] / DD);
        }
    }
    (void)out_size;

    fused_meanpool_bcast<<<2 * BB, NT>>>(Zimg, Zsnd, splits,
                                         (float4*)d_out, Tsnd);
}

// round 5
// speedup vs baseline: 1.1783x; 1.0057x over previous
#include <cuda_runtime.h>
#include <stdint.h>

#define BB   256          // batch (images / segments)
#define DD   512          // embedding dim
#define HWQ  256          // H*W spatial positions
#define D4   (DD/4)       // float4 columns per row = 128
#define NT   512          // threads per block
#define REP  8            // vector replicas in smem for bulk snd writes

__device__ __forceinline__ uint32_t smem_u32(const void* p) {
    uint32_t a;
    asm("{ .reg .u64 t; cvta.to.shared.u64 t, %1; cvt.u32.u64 %0, t; }"
        : "=r"(a) : "l"(p));
    return a;
}

__device__ __forceinline__ void bulk_store(void* gdst, uint32_t ssrc, uint32_t bytes) {
    asm volatile(
        "cp.async.bulk.global.shared::cta.bulk_group [%0], [%1], %2;"
        :: "l"(gdst), "r"(ssrc), "r"(bytes) : "memory");
}

__device__ __forceinline__ void bulk_commit() {
    asm volatile("cp.async.bulk.commit_group;" ::: "memory");
}

__device__ __forceinline__ void bulk_wait0() {
    asm volatile("cp.async.bulk.wait_group 0;" ::: "memory");
}

// ---------------------------------------------------------------------------
// One fused kernel, 2*BB blocks, no inter-block dependencies.
//   blocks [0, BB)    : snd. Scan splits in-smem, reduce segment b of Z_snd,
//                       replicate vector 8x in smem, TMA-bulk-store the
//                       contiguous 512 KiB of M_snd[b,:,:] as 32 x 16 KiB.
//   blocks [BB, 2*BB) : img. Spatial-reduce Z_img[j], TMA-bulk-store
//                       M_img[i,j,:] for all i as 256 x 2 KiB strided rows.
// Output layout: [ M_img (B,B,D) | M_snd (B,B,D) ].
// ---------------------------------------------------------------------------
__global__ __launch_bounds__(NT)
void fused_meanpool_bcast(const float* __restrict__ Zimg,
                          const float* __restrict__ Zsnd,
                          const int*   __restrict__ splits,
                          float4*      __restrict__ out,
                          long long T) {
    __shared__ long long s_scan[BB];       // 2 KiB  (snd only)
    __shared__ float4    s_part[4][D4];    // 8 KiB  (snd only)
    __shared__ __align__(16) float s_rep[REP * DD];  // 16 KiB replica buffer

    const int t = threadIdx.x;

    if (blockIdx.x < BB) {
        // =================== SND PATH ===================
        const int b = blockIdx.x;

        // --- in-block inclusive scan of splits (dtype-robust) ---
        if (t < BB) s_scan[t] = (long long)splits[t];
        __syncthreads();
#pragma unroll
        for (int off = 1; off < BB; off <<= 1) {
            long long v = (t >= off && t < BB) ? s_scan[t - off] : 0LL;
            __syncthreads();
            if (t < BB) s_scan[t] += v;
            __syncthreads();
        }
        if (s_scan[BB - 1] != T) {
            const long long* p64 = (const long long*)splits;
            __syncthreads();
            if (t < BB) s_scan[t] = p64[t];
            __syncthreads();
#pragma unroll
            for (int off = 1; off < BB; off <<= 1) {
                long long v = (t >= off && t < BB) ? s_scan[t - off] : 0LL;
                __syncthreads();
                if (t < BB) s_scan[t] += v;
                __syncthreads();
            }
        }
        __syncthreads();
        const long long start = (b == 0) ? 0LL : s_scan[b - 1];
        const long long len   = s_scan[b] - start;

        // --- segment reduce: 4 row-slices x 128 float4 columns ---
        const int col   = t & (D4 - 1);
        const int slice = t >> 7;
        long long r0 = start + (len * slice)       / 4;
        long long r1 = start + (len * (slice + 1)) / 4;

        const float4* p = reinterpret_cast<const float4*>(Zsnd);
        float4 acc = make_float4(0.f, 0.f, 0.f, 0.f);
        for (long long r = r0; r < r1; ++r) {
            float4 v = __ldcs(&p[r * D4 + col]);
            acc.x += v.x; acc.y += v.y; acc.z += v.z; acc.w += v.w;
        }
        s_part[slice][col] = acc;
        __syncthreads();

        if (slice == 0) {
            float4 a0 = s_part[0][col], a1 = s_part[1][col],
                   a2 = s_part[2][col], a3 = s_part[3][col];
            float inv = (len > 0) ? (1.0f / (float)len) : 0.0f;
            float4 o;
            o.x = (a0.x + a1.x + a2.x + a3.x) * inv;
            o.y = (a0.y + a1.y + a2.y + a3.y) * inv;
            o.z = (a0.z + a1.z + a2.z + a3.z) * inv;
            o.w = (a0.w + a1.w + a2.w + a3.w) * inv;
            // write all 8 replicas directly
            float4* rp = reinterpret_cast<float4*>(s_rep);
#pragma unroll
            for (int k = 0; k < REP; ++k)
                rp[k * D4 + col] = o;
        }
        __syncthreads();
        asm volatile("fence.proxy.async.shared::cta;" ::: "memory");

        // --- bulk-store M_snd[b,:,:] = 512 KiB contiguous = 32 x 16 KiB ---
        // 16 issuing threads (one per warp), 2 copies each.
        if ((t & 31) == 0) {
            const int wid = t >> 5;                  // 0..15
            uint32_t src = smem_u32(s_rep);
            char* dst = (char*)(out + (size_t)(BB + b) * (BB * D4));
            const uint32_t CSZ = REP * DD * 4;       // 16384
#pragma unroll
            for (int k = 0; k < 2; ++k) {
                int c = wid * 2 + k;                 // 0..31
                bulk_store(dst + (size_t)c * CSZ, src, CSZ);
            }
            bulk_commit();
            bulk_wait0();
        }

    } else {
        // =================== IMG PATH ===================
        const int j    = blockIdx.x - BB;
        const int wid  = t >> 5;
        const int lane = t & 31;

        // --- spatial reduce: 16 warps, each handles 32 d-rows of 64 float4 ---
        const float4* p = reinterpret_cast<const float4*>(
            Zimg + (size_t)j * DD * HWQ);
        for (int r = wid; r < DD; r += 16) {
            float4 a = __ldcs(&p[r * 64 + lane]);
            float4 b = __ldcs(&p[r * 64 + 32 + lane]);
            float s = (a.x + a.y) + (a.z + a.w) + (b.x + b.y) + (b.z + b.w);
#pragma unroll
            for (int o = 16; o > 0; o >>= 1)
                s += __shfl_down_sync(0xffffffffu, s, o);
            if (lane == 0)
                s_rep[r] = s * (1.0f / (float)HWQ);
        }
        __syncthreads();
        asm volatile("fence.proxy.async.shared::cta;" ::: "memory");

        // --- bulk-store M_img[i,j,:] for all i: 256 rows x 2 KiB, stride 512 KiB
        // 16 issuing threads, 16 rows each.
        if ((t & 31) == 0) {
            uint32_t src = smem_u32(s_rep);          // first 2 KiB holds z_img[j]
            char* dst = (char*)(out + (size_t)j * D4);
            const uint32_t RSZ = DD * 4;             // 2048
            const size_t   STR = (size_t)BB * D4 * 16;  // 512 KiB row stride
#pragma unroll
            for (int k = 0; k < 16; ++k) {
                int i = wid * 16 + k;                // 0..255
                bulk_store(dst + (size_t)i * STR, src, RSZ);
            }
            bulk_commit();
            bulk_wait0();
        }
    }
}

// ---------------------------------------------------------------------------
extern "C" void kernel_launch(void* const* d_in, const int* in_sizes, int n_in,
                              void* d_out, int out_size) {
    // Identify inputs by element count:
    //   Z_img: 33,554,432   Z_snd: 16,777,216   splits: 256
    const float* Zimg   = nullptr;
    const float* Zsnd   = nullptr;
    const int*   splits = nullptr;
    long long    Tsnd   = 0;

    for (int i = 0; i < n_in; ++i) {
        if (in_sizes[i] == BB) {
            splits = (const int*)d_in[i];
        } else if (in_sizes[i] == BB * DD * HWQ) {
            Zimg = (const float*)d_in[i];
        } else {
            Zsnd = (const float*)d_in[i];
            Tsnd = (long long)(in_sizes[i] / DD);
        }
    }
    (void)out_size;

    fused_meanpool_bcast<<<2 * BB, NT>>>(Zimg, Zsnd, splits,
                                         (float4*)d_out, Tsnd);
}

// round 6
// speedup vs baseline: 1.2073x; 1.0246x over previous
#include <cuda_runtime.h>
#include <stdint.h>

#define BB   256          // batch (images / segments)
#define DD   512          // embedding dim
#define HWQ  256          // H*W spatial positions
#define D4   (DD/4)       // float4 columns per row = 128
#define NT   512          // threads per block
#define REP  8            // vector replicas in smem for bulk snd writes

__device__ __forceinline__ uint32_t smem_u32(const void* p) {
    uint32_t a;
    asm("{ .reg .u64 t; cvta.to.shared.u64 t, %1; cvt.u32.u64 %0, t; }"
        : "=r"(a) : "l"(p));
    return a;
}

__device__ __forceinline__ uint64_t mkpolicy_evict_last() {
    uint64_t p;
    asm("createpolicy.fractional.L2::evict_last.b64 %0, 1.0;" : "=l"(p));
    return p;
}
__device__ __forceinline__ uint64_t mkpolicy_evict_first() {
    uint64_t p;
    asm("createpolicy.fractional.L2::evict_first.b64 %0, 1.0;" : "=l"(p));
    return p;
}

// float4 global load with an L2 cache policy
__device__ __forceinline__ float4 ldg_pol(const float4* p, uint64_t pol) {
    float4 v;
    asm volatile("ld.global.L2::cache_hint.v4.f32 {%0,%1,%2,%3}, [%4], %5;"
                 : "=f"(v.x), "=f"(v.y), "=f"(v.z), "=f"(v.w)
                 : "l"(p), "l"(pol));
    return v;
}

// TMA bulk store smem -> gmem with L2 evict_first policy
__device__ __forceinline__ void bulk_store(void* gdst, uint32_t ssrc,
                                           uint32_t bytes, uint64_t pol) {
    asm volatile(
        "cp.async.bulk.global.shared::cta.bulk_group.L2::cache_hint "
        "[%0], [%1], %2, %3;"
        :: "l"(gdst), "r"(ssrc), "r"(bytes), "l"(pol) : "memory");
}
__device__ __forceinline__ void bulk_commit() {
    asm volatile("cp.async.bulk.commit_group;" ::: "memory");
}
__device__ __forceinline__ void bulk_wait0() {
    asm volatile("cp.async.bulk.wait_group 0;" ::: "memory");
}

// ---------------------------------------------------------------------------
// One fused kernel, 2*BB blocks (all resident in one wave).
//   blocks [0, BB)    : snd. Scan splits in-smem, reduce segment b of Z_snd
//                       (L2 evict_last: Z_snd = 64 MiB stays L2-resident
//                       across graph replays), replicate vector 8x in smem,
//                       TMA-bulk-store the contiguous 512 KiB of M_snd[b,:,:].
//   blocks [BB, 2*BB) : img. Spatial-reduce Z_img[j] (evict_first reads),
//                       TMA-bulk-store M_img[i,j,:] for all i (256 x 2 KiB).
// All stores use L2 evict_first so write traffic doesn't displace Z_snd.
// Output layout: [ M_img (B,B,D) | M_snd (B,B,D) ].
// ---------------------------------------------------------------------------
__global__ __launch_bounds__(NT)
void fused_meanpool_bcast(const float* __restrict__ Zimg,
                          const float* __restrict__ Zsnd,
                          const int*   __restrict__ splits,
                          float4*      __restrict__ out,
                          long long T) {
    __shared__ long long s_scan[BB];       // 2 KiB  (snd only)
    __shared__ float4    s_part[4][D4];    // 8 KiB  (snd only)
    __shared__ __align__(16) float s_rep[REP * DD];  // 16 KiB replica buffer

    const int t = threadIdx.x;
    const uint64_t pol_wr = mkpolicy_evict_first();

    if (blockIdx.x < BB) {
        // =================== SND PATH ===================
        const int b = blockIdx.x;
        const uint64_t pol_rd = mkpolicy_evict_last();

        // --- in-block inclusive scan of splits (dtype-robust) ---
        if (t < BB) s_scan[t] = (long long)splits[t];
        __syncthreads();
#pragma unroll
        for (int off = 1; off < BB; off <<= 1) {
            long long v = (t >= off && t < BB) ? s_scan[t - off] : 0LL;
            __syncthreads();
            if (t < BB) s_scan[t] += v;
            __syncthreads();
        }
        if (s_scan[BB - 1] != T) {
            const long long* p64 = (const long long*)splits;
            __syncthreads();
            if (t < BB) s_scan[t] = p64[t];
            __syncthreads();
#pragma unroll
            for (int off = 1; off < BB; off <<= 1) {
                long long v = (t >= off && t < BB) ? s_scan[t - off] : 0LL;
                __syncthreads();
                if (t < BB) s_scan[t] += v;
                __syncthreads();
            }
        }
        __syncthreads();
        const long long start = (b == 0) ? 0LL : s_scan[b - 1];
        const long long len   = s_scan[b] - start;

        // --- segment reduce: 4 row-slices x 128 float4 columns ---
        const int col   = t & (D4 - 1);
        const int slice = t >> 7;
        long long r0 = start + (len * slice)       / 4;
        long long r1 = start + (len * (slice + 1)) / 4;

        const float4* p = reinterpret_cast<const float4*>(Zsnd);
        float4 acc = make_float4(0.f, 0.f, 0.f, 0.f);
        for (long long r = r0; r < r1; ++r) {
            float4 v = ldg_pol(&p[r * D4 + col], pol_rd);
            acc.x += v.x; acc.y += v.y; acc.z += v.z; acc.w += v.w;
        }
        s_part[slice][col] = acc;
        __syncthreads();

        if (slice == 0) {
            float4 a0 = s_part[0][col], a1 = s_part[1][col],
                   a2 = s_part[2][col], a3 = s_part[3][col];
            float inv = (len > 0) ? (1.0f / (float)len) : 0.0f;
            float4 o;
            o.x = (a0.x + a1.x + a2.x + a3.x) * inv;
            o.y = (a0.y + a1.y + a2.y + a3.y) * inv;
            o.z = (a0.z + a1.z + a2.z + a3.z) * inv;
            o.w = (a0.w + a1.w + a2.w + a3.w) * inv;
            float4* rp = reinterpret_cast<float4*>(s_rep);
#pragma unroll
            for (int k = 0; k < REP; ++k)
                rp[k * D4 + col] = o;
        }
        __syncthreads();
        asm volatile("fence.proxy.async.shared::cta;" ::: "memory");

        // --- bulk-store M_snd[b,:,:] = 512 KiB contiguous = 32 x 16 KiB ---
        if ((t & 31) == 0) {
            const int wid = t >> 5;                  // 0..15
            uint32_t src = smem_u32(s_rep);
            char* dst = (char*)(out + (size_t)(BB + b) * (BB * D4));
            const uint32_t CSZ = REP * DD * 4;       // 16384
#pragma unroll
            for (int k = 0; k < 2; ++k) {
                int c = wid * 2 + k;                 // 0..31
                bulk_store(dst + (size_t)c * CSZ, src, CSZ, pol_wr);
            }
            bulk_commit();
            bulk_wait0();
        }

    } else {
        // =================== IMG PATH ===================
        const int j    = blockIdx.x - BB;
        const int wid  = t >> 5;
        const int lane = t & 31;
        const uint64_t pol_img = mkpolicy_evict_first();

        // --- spatial reduce: 16 warps, each handles 32 d-rows of 64 float4 ---
        const float4* p = reinterpret_cast<const float4*>(
            Zimg + (size_t)j * DD * HWQ);
        for (int r = wid; r < DD; r += 16) {
            float4 a = ldg_pol(&p[r * 64 + lane],      pol_img);
            float4 b = ldg_pol(&p[r * 64 + 32 + lane], pol_img);
            float s = (a.x + a.y) + (a.z + a.w) + (b.x + b.y) + (b.z + b.w);
#pragma unroll
            for (int o = 16; o > 0; o >>= 1)
                s += __shfl_down_sync(0xffffffffu, s, o);
            if (lane == 0)
                s_rep[r] = s * (1.0f / (float)HWQ);
        }
        __syncthreads();
        asm volatile("fence.proxy.async.shared::cta;" ::: "memory");

        // --- bulk-store M_img[i,j,:] for all i: 256 rows x 2 KiB, stride 512 KiB
        if ((t & 31) == 0) {
            uint32_t src = smem_u32(s_rep);          // first 2 KiB = z_img[j]
            char* dst = (char*)(out + (size_t)j * D4);
            const uint32_t RSZ = DD * 4;             // 2048
            const size_t   STR = (size_t)BB * D4 * 16;  // 512 KiB row stride
#pragma unroll
            for (int k = 0; k < 16; ++k) {
                int i = wid * 16 + k;                // 0..255
                bulk_store(dst + (size_t)i * STR, src, RSZ, pol_wr);
            }
            bulk_commit();
            bulk_wait0();
        }
    }
}

// ---------------------------------------------------------------------------
extern "C" void kernel_launch(void* const* d_in, const int* in_sizes, int n_in,
                              void* d_out, int out_size) {
    // Identify inputs by element count:
    //   Z_img: 33,554,432   Z_snd: 16,777,216   splits: 256
    const float* Zimg   = nullptr;
    const float* Zsnd   = nullptr;
    const int*   splits = nullptr;
    long long    Tsnd   = 0;

    for (int i = 0; i < n_in; ++i) {
        if (in_sizes[i] == BB) {
            splits = (const int*)d_in[i];
        } else if (in_sizes[i] == BB * DD * HWQ) {
            Zimg = (const float*)d_in[i];
        } else {
            Zsnd = (const float*)d_in[i];
            Tsnd = (long long)(in_sizes[i] / DD);
        }
    }
    (void)out_size;

    fused_meanpool_bcast<<<2 * BB, NT>>>(Zimg, Zsnd, splits,
                                         (float4*)d_out, Tsnd);
}

// round 7
// speedup vs baseline: 1.2382x; 1.0256x over previous
#include <cuda_runtime.h>
#include <stdint.h>

#define BB   256          // batch (images / segments)
#define DD   512          // embedding dim
#define HWQ  256          // H*W spatial positions
#define NT   256          // threads per block
#define DH   256          // d-half size (DD/2)
#define DH4  64           // float4s per half-vector

__device__ __forceinline__ uint32_t smem_u32(const void* p) {
    uint32_t a;
    asm("{ .reg .u64 t; cvta.to.shared.u64 t, %1; cvt.u32.u64 %0, t; }"
        : "=r"(a) : "l"(p));
    return a;
}
__device__ __forceinline__ uint64_t mkpolicy_evict_last() {
    uint64_t p; asm("createpolicy.fractional.L2::evict_last.b64 %0, 1.0;" : "=l"(p)); return p;
}
__device__ __forceinline__ uint64_t mkpolicy_evict_first() {
    uint64_t p; asm("createpolicy.fractional.L2::evict_first.b64 %0, 1.0;" : "=l"(p)); return p;
}
__device__ __forceinline__ float4 ldg_pol(const float4* p, uint64_t pol) {
    float4 v;
    asm volatile("ld.global.L2::cache_hint.v4.f32 {%0,%1,%2,%3}, [%4], %5;"
                 : "=f"(v.x), "=f"(v.y), "=f"(v.z), "=f"(v.w)
                 : "l"(p), "l"(pol));
    return v;
}
__device__ __forceinline__ void bulk_store(void* gdst, uint32_t ssrc,
                                           uint32_t bytes, uint64_t pol) {
    asm volatile("cp.async.bulk.global.shared::cta.bulk_group.L2::cache_hint "
                 "[%0], [%1], %2, %3;"
                 :: "l"(gdst), "r"(ssrc), "r"(bytes), "l"(pol) : "memory");
}
__device__ __forceinline__ void bulk_commit() {
    asm volatile("cp.async.bulk.commit_group;" ::: "memory");
}
__device__ __forceinline__ void bulk_wait0() {
    asm volatile("cp.async.bulk.wait_group 0;" ::: "memory");
}

// ---------------------------------------------------------------------------
// 1024 uniform blocks x 256 threads, single wave at 8 blocks/SM.
//   bid in [0,512)    : img item (j = bid>>1, h = bid&1)
//       reduce d-rows [256h,256h+256) of Z_img[j]  (256 KiB contiguous read)
//       write M_img[i, j, 256h:256h+256) for all i (256 x 1 KiB, stride 512 KiB)
//   bid in [512,1024) : snd item (b = (bid-512)>>1, h)
//       scan splits in-smem, reduce cols [256h,256h+256) of segment b
//       (128 KiB read), write M_snd[b, i, 256h:...) (256 x 1 KiB, stride 2 KiB)
// Output layout: [ M_img (B,B,D) | M_snd (B,B,D) ].
// ---------------------------------------------------------------------------
__global__ __launch_bounds__(NT, 8)
void fused_meanpool_bcast(const float* __restrict__ Zimg,
                          const float* __restrict__ Zsnd,
                          const int*   __restrict__ splits,
                          float*       __restrict__ out,
                          long long T) {
    __shared__ long long s_scan[BB];                   // 2 KiB (snd only)
    __shared__ float4    s_part[4][DH4];               // 4 KiB (snd only)
    __shared__ __align__(16) float s_half[DH];         // 1 KiB half-vector

    const int t    = threadIdx.x;
    const int wid  = t >> 5;
    const int lane = t & 31;
    const uint64_t pol_wr = mkpolicy_evict_first();
    const size_t NIMG_BYTES = (size_t)BB * BB * DD * 4;   // 128 MiB

    if (blockIdx.x < 512) {
        // =================== IMG ITEM ===================
        const int j = blockIdx.x >> 1;
        const int h = blockIdx.x & 1;
        const uint64_t pol_rd = mkpolicy_evict_first();

        // rows [256h, 256h+256): contiguous 256 KiB slab
        const float4* p = reinterpret_cast<const float4*>(
            Zimg + ((size_t)j * DD + (size_t)h * DH) * HWQ);

        // 8 warps x 32 rows each; per row: 64 float4, 2 per lane
        for (int k = 0; k < 32; ++k) {
            int lr = wid * 32 + k;                     // local d-row 0..255
            float4 a = ldg_pol(&p[(size_t)lr * 64 + lane],      pol_rd);
            float4 b = ldg_pol(&p[(size_t)lr * 64 + 32 + lane], pol_rd);
            float s = (a.x + a.y) + (a.z + a.w) + (b.x + b.y) + (b.z + b.w);
#pragma unroll
            for (int o = 16; o > 0; o >>= 1)
                s += __shfl_down_sync(0xffffffffu, s, o);
            if (lane == 0)
                s_half[lr] = s * (1.0f / (float)HWQ);
        }
        __syncthreads();
        asm volatile("fence.proxy.async.shared::cta;" ::: "memory");

        // write 256 rows x 1 KiB at 512 KiB stride
        if (lane == 0) {
            uint32_t src = smem_u32(s_half);
            char* dst0 = (char*)out + ((size_t)j * DD + (size_t)h * DH) * 4;
            const size_t STR = (size_t)BB * DD * 4;    // 512 KiB
#pragma unroll 4
            for (int k = 0; k < 32; ++k) {
                int i = wid * 32 + k;
                bulk_store(dst0 + (size_t)i * STR, src, DH * 4, pol_wr);
            }
            bulk_commit();
            bulk_wait0();
        }

    } else {
        // =================== SND ITEM ===================
        const int id = blockIdx.x - 512;
        const int b  = id >> 1;
        const int h  = id & 1;
        const uint64_t pol_rd = mkpolicy_evict_last();

        // --- in-block inclusive scan of splits (dtype-robust) ---
        s_scan[t] = (long long)splits[t];
        __syncthreads();
#pragma unroll
        for (int off = 1; off < BB; off <<= 1) {
            long long v = (t >= off) ? s_scan[t - off] : 0LL;
            __syncthreads();
            s_scan[t] += v;
            __syncthreads();
        }
        if (s_scan[BB - 1] != T) {
            const long long* p64 = (const long long*)splits;
            __syncthreads();
            s_scan[t] = p64[t];
            __syncthreads();
#pragma unroll
            for (int off = 1; off < BB; off <<= 1) {
                long long v = (t >= off) ? s_scan[t - off] : 0LL;
                __syncthreads();
                s_scan[t] += v;
                __syncthreads();
            }
        }
        __syncthreads();
        const long long start = (b == 0) ? 0LL : s_scan[b - 1];
        const long long len   = s_scan[b] - start;

        // --- reduce cols [64h..64h+64) float4 over segment rows ---
        const int col   = t & (DH4 - 1);               // 0..63
        const int slice = t >> 6;                      // 0..3
        long long r0 = start + (len * slice)       / 4;
        long long r1 = start + (len * (slice + 1)) / 4;

        const float4* p = reinterpret_cast<const float4*>(Zsnd);
        float4 acc = make_float4(0.f, 0.f, 0.f, 0.f);
        for (long long r = r0; r < r1; ++r) {
            float4 v = ldg_pol(&p[r * (DD / 4) + h * DH4 + col], pol_rd);
            acc.x += v.x; acc.y += v.y; acc.z += v.z; acc.w += v.w;
        }
        s_part[slice][col] = acc;
        __syncthreads();

        if (slice == 0) {
            float4 a0 = s_part[0][col], a1 = s_part[1][col],
                   a2 = s_part[2][col], a3 = s_part[3][col];
            float inv = (len > 0) ? (1.0f / (float)len) : 0.0f;
            float4 o;
            o.x = (a0.x + a1.x + a2.x + a3.x) * inv;
            o.y = (a0.y + a1.y + a2.y + a3.y) * inv;
            o.z = (a0.z + a1.z + a2.z + a3.z) * inv;
            o.w = (a0.w + a1.w + a2.w + a3.w) * inv;
            reinterpret_cast<float4*>(s_half)[col] = o;
        }
        __syncthreads();
        asm volatile("fence.proxy.async.shared::cta;" ::: "memory");

        // write 256 rows x 1 KiB at 2 KiB stride
        if (lane == 0) {
            uint32_t src = smem_u32(s_half);
            char* dst0 = (char*)out + NIMG_BYTES
                       + ((size_t)b * BB * DD + (size_t)h * DH) * 4;
            const size_t STR = (size_t)DD * 4;         // 2 KiB
#pragma unroll 4
            for (int k = 0; k < 32; ++k) {
                int i = wid * 32 + k;
                bulk_store(dst0 + (size_t)i * STR, src, DH * 4, pol_wr);
            }
            bulk_commit();
            bulk_wait0();
        }
    }
}

// ---------------------------------------------------------------------------
extern "C" void kernel_launch(void* const* d_in, const int* in_sizes, int n_in,
                              void* d_out, int out_size) {
    // Identify inputs by element count:
    //   Z_img: 33,554,432   Z_snd: 16,777,216   splits: 256
    const float* Zimg   = nullptr;
    const float* Zsnd   = nullptr;
    const int*   splits = nullptr;
    long long    Tsnd   = 0;

    for (int i = 0; i < n_in; ++i) {
        if (in_sizes[i] == BB) {
            splits = (const int*)d_in[i];
        } else if (in_sizes[i] == BB * DD * HWQ) {
            Zimg = (const float*)d_in[i];
        } else {
            Zsnd = (const float*)d_in[i];
            Tsnd = (long long)(in_sizes[i] / DD);
        }
    }
    (void)out_size;

    fused_meanpool_bcast<<<1024, NT>>>(Zimg, Zsnd, splits,
                                       (float*)d_out, Tsnd);
}